// round 1
// baseline (speedup 1.0000x reference)
#include <cuda_runtime.h>

#define FULL_MASK 0xffffffffu

// ---------- packed f32x2 + fast-math helpers ----------
__device__ __forceinline__ float2 ffma2(float2 a, float2 b, float2 c) {
    unsigned long long au = *reinterpret_cast<unsigned long long*>(&a);
    unsigned long long bu = *reinterpret_cast<unsigned long long*>(&b);
    unsigned long long cu = *reinterpret_cast<unsigned long long*>(&c);
    unsigned long long du;
    asm("fma.rn.f32x2 %0, %1, %2, %3;" : "=l"(du) : "l"(au), "l"(bu), "l"(cu));
    return *reinterpret_cast<float2*>(&du);
}

__device__ __forceinline__ float2 fadd2(float2 a, float2 b) {
    unsigned long long au = *reinterpret_cast<unsigned long long*>(&a);
    unsigned long long bu = *reinterpret_cast<unsigned long long*>(&b);
    unsigned long long du;
    asm("add.rn.f32x2 %0, %1, %2;" : "=l"(du) : "l"(au), "l"(bu));
    return *reinterpret_cast<float2*>(&du);
}

__device__ __forceinline__ float ex2a(float x) {
    float r;
    asm("ex2.approx.f32 %0, %1;" : "=f"(r) : "f"(x));
    return r;
}

__device__ __forceinline__ float rcpa(float x) {
    float r;
    asm("rcp.approx.f32 %0, %1;" : "=f"(r) : "f"(x));
    return r;
}

// H = 32 hidden units, 4H = 128 gates, I = 1 input, T = 512 steps, B = 8192.
// One warp per batch element. Lane j owns hidden unit j and computes gates
// (i_j, f_j) packed and (g_j, o_j) packed via fma.rn.f32x2.
//
// Activation prescales folded into weights:
//   sigmoid(a) = rcp(1 + ex2(P_SIG * a)),  P_SIG  = -log2(e)
//   tanh(a)    = 1 - 2*rcp(1 + ex2(P_TANH * a)), P_TANH = 2*log2(e)

__global__ void __launch_bounds__(128, 2) lstm_h32_kernel(
    const float* __restrict__ x,      // [B, 512, 1]
    const float* __restrict__ W_ih,   // [128, 1]
    const float* __restrict__ W_hh,   // [128, 32]
    const float* __restrict__ b_ih,   // [128]
    const float* __restrict__ b_hh,   // [128]
    const float* __restrict__ W_lin,  // [1, 32]
    const float* __restrict__ b_lin,  // [1]
    float* __restrict__ out)          // [B, 1]
{
    // W_hh staged with stride 33 to avoid 32-way bank conflicts in the
    // per-lane weight gather below.
    __shared__ float swhh[128 * 33];
    // Per-warp double-buffered duplicated-h ring: hbuf[warp][parity][k] = (h_k, h_k)
    __shared__ __align__(16) float2 hbuf[4][2][32];

    const int tid = threadIdx.x;
    for (int i = tid; i < 128 * 32; i += 128) {
        swhh[(i >> 5) * 33 + (i & 31)] = W_hh[i];
    }
    __syncthreads();

    const int w = tid >> 5;       // warp in CTA (0..3)
    const int j = tid & 31;       // lane = hidden unit
    const int b = blockIdx.x * 4 + w;  // batch element

    const float P_SIG  = -1.4426950408889634f;  // -log2(e)
    const float P_TANH =  2.8853900817779268f;  //  2*log2(e)

    // Per-lane recurrent weights, prescaled, packed by gate pair.
    // wif[k] = (P_SIG*W_hh[i_j,k],  P_SIG*W_hh[f_j,k])
    // wgo[k] = (P_TANH*W_hh[g_j,k], P_SIG*W_hh[o_j,k])
    float2 wif[32], wgo[32];
    #pragma unroll
    for (int k = 0; k < 32; ++k) {
        wif[k] = make_float2(P_SIG  * swhh[(j      ) * 33 + k],
                             P_SIG  * swhh[(j + 32 ) * 33 + k]);
        wgo[k] = make_float2(P_TANH * swhh[(j + 64 ) * 33 + k],
                             P_SIG  * swhh[(j + 96 ) * 33 + k]);
    }

    // Input weights + (b_ih + b_hh), prescaled, packed identically.
    const float2 pwih_if = make_float2(P_SIG  * W_ih[j],
                                       P_SIG  * W_ih[j + 32]);
    const float2 pwih_go = make_float2(P_TANH * W_ih[j + 64],
                                       P_SIG  * W_ih[j + 96]);
    const float2 pb_if = make_float2(P_SIG  * (b_ih[j     ] + b_hh[j     ]),
                                     P_SIG  * (b_ih[j + 32] + b_hh[j + 32]));
    const float2 pb_go = make_float2(P_TANH * (b_ih[j + 64] + b_hh[j + 64]),
                                     P_SIG  * (b_ih[j + 96] + b_hh[j + 96]));

    const float* xb = x + (size_t)b * 512;

    float c = 0.0f, h = 0.0f;
    hbuf[w][0][j] = make_float2(0.0f, 0.0f);
    __syncwarp();

    for (int t0 = 0; t0 < 512; t0 += 32) {
        // Coalesced prefetch of 32 timesteps of x for this batch.
        const float xv = xb[t0 + j];

        for (int tm = 0; tm < 32; tm += 8) {
            #pragma unroll
            for (int u = 0; u < 8; ++u) {
                const int tt = tm + u;                 // step within 32-chunk
                const int pr = tt & 1;                 // read-buffer parity
                const float xt = __shfl_sync(FULL_MASK, xv, tt);
                const float2 xd = make_float2(xt, xt);

                float2 aif  = ffma2(xd, pwih_if, pb_if);
                float2 ago  = ffma2(xd, pwih_go, pb_go);
                float2 aif2 = make_float2(0.0f, 0.0f);
                float2 ago2 = make_float2(0.0f, 0.0f);

                const float4* hb =
                    reinterpret_cast<const float4*>(&hbuf[w][pr][0]);
                #pragma unroll
                for (int q = 0; q < 16; ++q) {
                    const float4 hv = hb[q];           // broadcast LDS.128
                    const float2 h0 = make_float2(hv.x, hv.y);
                    const float2 h1 = make_float2(hv.z, hv.w);
                    aif  = ffma2(h0, wif[2 * q    ], aif );
                    ago  = ffma2(h0, wgo[2 * q    ], ago );
                    aif2 = ffma2(h1, wif[2 * q + 1], aif2);
                    ago2 = ffma2(h1, wgo[2 * q + 1], ago2);
                }
                aif = fadd2(aif, aif2);
                ago = fadd2(ago, ago2);

                // Activations (prescales already applied inside the dots).
                const float si = rcpa(1.0f + ex2a(aif.x));                  // sigmoid(i)
                const float sf = rcpa(1.0f + ex2a(aif.y));                  // sigmoid(f)
                const float tg = fmaf(-2.0f, rcpa(1.0f + ex2a(ago.x)), 1.0f); // tanh(g)
                const float so = rcpa(1.0f + ex2a(ago.y));                  // sigmoid(o)

                c = fmaf(sf, c, si * tg);
                const float tc = fmaf(-2.0f, rcpa(1.0f + ex2a(c * P_TANH)), 1.0f);
                h = so * tc;

                hbuf[w][pr ^ 1][j] = make_float2(h, h);  // STS.64
                __syncwarp();
            }
        }
    }

    // out[b] = dot(h, W_lin) + b_lin  (warp reduction)
    float v = h * W_lin[j];
    #pragma unroll
    for (int off = 16; off; off >>= 1)
        v += __shfl_xor_sync(FULL_MASK, v, off);
    if (j == 0) out[b] = v + b_lin[0];
}

extern "C" void kernel_launch(void* const* d_in, const int* in_sizes, int n_in,
                              void* d_out, int out_size) {
    const float* x     = (const float*)d_in[0];
    const float* W_ih  = (const float*)d_in[1];
    const float* W_hh  = (const float*)d_in[2];
    const float* b_ih  = (const float*)d_in[3];
    const float* b_hh  = (const float*)d_in[4];
    const float* W_lin = (const float*)d_in[5];
    const float* b_lin = (const float*)d_in[6];
    float* out = (float*)d_out;

    // B = 8192 batches, 4 warps (batches) per 128-thread CTA -> 2048 CTAs.
    lstm_h32_kernel<<<2048, 128>>>(x, W_ih, W_hh, b_ih, b_hh, W_lin, b_lin, out);
}

// round 2
// speedup vs baseline: 1.0383x; 1.0383x over previous
#include <cuda_runtime.h>

#define FULL_MASK 0xffffffffu

// ---------- packed f32x2 + fast-math helpers ----------
__device__ __forceinline__ float2 ffma2(float2 a, float2 b, float2 c) {
    unsigned long long au = *reinterpret_cast<unsigned long long*>(&a);
    unsigned long long bu = *reinterpret_cast<unsigned long long*>(&b);
    unsigned long long cu = *reinterpret_cast<unsigned long long*>(&c);
    unsigned long long du;
    asm("fma.rn.f32x2 %0, %1, %2, %3;" : "=l"(du) : "l"(au), "l"(bu), "l"(cu));
    return *reinterpret_cast<float2*>(&du);
}

__device__ __forceinline__ float2 fadd2(float2 a, float2 b) {
    unsigned long long au = *reinterpret_cast<unsigned long long*>(&a);
    unsigned long long bu = *reinterpret_cast<unsigned long long*>(&b);
    unsigned long long du;
    asm("add.rn.f32x2 %0, %1, %2;" : "=l"(du) : "l"(au), "l"(bu));
    return *reinterpret_cast<float2*>(&du);
}

__device__ __forceinline__ float ex2a(float x) {
    float r; asm("ex2.approx.f32 %0, %1;" : "=f"(r) : "f"(x)); return r;
}
__device__ __forceinline__ float rcpa(float x) {
    float r; asm("rcp.approx.f32 %0, %1;" : "=f"(r) : "f"(x)); return r;
}

// H=32, 4H=128, I=1, T=512, B=8192.
// One warp handles TWO batch elements (shared weight registers, two
// independent recurrence chains for latency hiding). Lane j owns hidden
// unit j / gate rows {j, j+32, j+64, j+96}.
//
// k-packed dots: acc[g] += (h_{2q}, h_{2q+1}) * (W[g_row, 2q], W[g_row, 2q+1])
// so the h operand comes straight out of a non-duplicated smem h vector
// (8 broadcast LDS.128 per batch-step).
//
// Activation prescales folded into weights/biases:
//   sigmoid(a) = rcp(1 + ex2(P_SIG * a)),   P_SIG  = -log2(e)
//   tanh(a)    = 1 - 2*rcp(1 + ex2(P_TANH * a)), P_TANH = 2*log2(e)

__global__ void __launch_bounds__(128, 2) lstm_h32_kernel(
    const float* __restrict__ x,      // [B, 512, 1]
    const float* __restrict__ W_ih,   // [128, 1]
    const float* __restrict__ W_hh,   // [128, 32]
    const float* __restrict__ b_ih,   // [128]
    const float* __restrict__ b_hh,   // [128]
    const float* __restrict__ W_lin,  // [1, 32]
    const float* __restrict__ b_lin,  // [1]
    float* __restrict__ out)          // [B, 1]
{
    // Weight staging: stride 34 floats (even, for aligned float2 reads;
    // 2-way 64-bit conflicts only in the prologue gather — irrelevant).
    __shared__ __align__(16) float swhh[128 * 34];
    // h ring: [warp][batch-in-warp][parity][k]
    __shared__ __align__(16) float hbuf[4][2][2][32];

    const int tid = threadIdx.x;
    for (int i = tid; i < 128 * 32; i += 128)
        swhh[(i >> 5) * 34 + (i & 31)] = W_hh[i];
    __syncthreads();

    const int w = tid >> 5;
    const int j = tid & 31;
    const int b0 = (blockIdx.x * 4 + w) * 2;   // first of the 2 batches

    const float P_SIG  = -1.4426950408889634f;
    const float P_TANH =  2.8853900817779268f;
    const float PS[4] = {P_SIG, P_SIG, P_TANH, P_SIG};

    // Per-lane recurrent weights, prescaled, k-pair packed: wv[g][q]
    float2 wv[4][16];
    #pragma unroll
    for (int g = 0; g < 4; ++g) {
        const float* row = &swhh[(j + 32 * g) * 34];
        #pragma unroll
        for (int q = 0; q < 16; ++q) {
            float2 t = *reinterpret_cast<const float2*>(row + 2 * q);
            wv[g][q] = make_float2(PS[g] * t.x, PS[g] * t.y);
        }
    }

    float pwih[4], pb[4];
    #pragma unroll
    for (int g = 0; g < 4; ++g) {
        pwih[g] = PS[g] * W_ih[j + 32 * g];
        pb[g]   = PS[g] * (b_ih[j + 32 * g] + b_hh[j + 32 * g]);
    }

    const float* xb0 = x + (size_t)(b0    ) * 512;
    const float* xb1 = x + (size_t)(b0 + 1) * 512;

    float c[2] = {0.0f, 0.0f};
    float h[2] = {0.0f, 0.0f};
    hbuf[w][0][0][j] = 0.0f;
    hbuf[w][1][0][j] = 0.0f;
    __syncwarp();

    for (int t0 = 0; t0 < 512; t0 += 32) {
        // Coalesced prefetch of 32 timesteps for both batches.
        const float xv0 = xb0[t0 + j];
        const float xv1 = xb1[t0 + j];

        for (int tm = 0; tm < 32; tm += 8) {
            #pragma unroll
            for (int u = 0; u < 8; ++u) {
                const int tt = tm + u;
                const int pr = tt & 1;
                const float xt[2] = {__shfl_sync(FULL_MASK, xv0, tt),
                                     __shfl_sync(FULL_MASK, xv1, tt)};

                #pragma unroll
                for (int bb = 0; bb < 2; ++bb) {
                    float2 acc0[4], acc1[4];
                    #pragma unroll
                    for (int g = 0; g < 4; ++g) {
                        acc0[g] = make_float2(fmaf(xt[bb], pwih[g], pb[g]), 0.0f);
                        acc1[g] = make_float2(0.0f, 0.0f);
                    }
                    const float4* hb =
                        reinterpret_cast<const float4*>(&hbuf[w][bb][pr][0]);
                    #pragma unroll
                    for (int q2 = 0; q2 < 8; ++q2) {
                        const float4 hv = hb[q2];      // broadcast LDS.128
                        const float2 h0 = make_float2(hv.x, hv.y);
                        const float2 h1 = make_float2(hv.z, hv.w);
                        #pragma unroll
                        for (int g = 0; g < 4; ++g) {
                            acc0[g] = ffma2(h0, wv[g][2 * q2    ], acc0[g]);
                            acc1[g] = ffma2(h1, wv[g][2 * q2 + 1], acc1[g]);
                        }
                    }
                    float a[4];
                    #pragma unroll
                    for (int g = 0; g < 4; ++g) {
                        const float2 m = fadd2(acc0[g], acc1[g]);
                        a[g] = m.x + m.y;
                    }

                    const float si = rcpa(1.0f + ex2a(a[0]));
                    const float sf = rcpa(1.0f + ex2a(a[1]));
                    const float tg = fmaf(-2.0f, rcpa(1.0f + ex2a(a[2])), 1.0f);
                    const float so = rcpa(1.0f + ex2a(a[3]));

                    c[bb] = fmaf(sf, c[bb], si * tg);
                    const float tc =
                        fmaf(-2.0f, rcpa(1.0f + ex2a(c[bb] * P_TANH)), 1.0f);
                    h[bb] = so * tc;
                    hbuf[w][bb][pr ^ 1][j] = h[bb];    // STS.32
                }
                __syncwarp();
            }
        }
    }

    // out[b] = dot(h, W_lin) + b_lin for both batches (warp reductions)
    const float wl = W_lin[j];
    #pragma unroll
    for (int bb = 0; bb < 2; ++bb) {
        float v = h[bb] * wl;
        #pragma unroll
        for (int off = 16; off; off >>= 1)
            v += __shfl_xor_sync(FULL_MASK, v, off);
        if (j == 0) out[b0 + bb] = v + b_lin[0];
    }
}

extern "C" void kernel_launch(void* const* d_in, const int* in_sizes, int n_in,
                              void* d_out, int out_size) {
    const float* x     = (const float*)d_in[0];
    const float* W_ih  = (const float*)d_in[1];
    const float* W_hh  = (const float*)d_in[2];
    const float* b_ih  = (const float*)d_in[3];
    const float* b_hh  = (const float*)d_in[4];
    const float* W_lin = (const float*)d_in[5];
    const float* b_lin = (const float*)d_in[6];
    float* out = (float*)d_out;

    // 8192 batches / (4 warps * 2 batches per warp) = 1024 CTAs.
    lstm_h32_kernel<<<1024, 128>>>(x, W_ih, W_hh, b_ih, b_hh, W_lin, b_lin, out);
}